// round 1
// baseline (speedup 1.0000x reference)
#include <cuda_runtime.h>

// Problem constants
#define KN 4096      // nodes
#define KF 32        // features
#define KHF 64       // heads*features
#define KNHID 64
#define KC 10
#define KE 65536     // edges
#define KG 13        // branches
#define KNN (KN*KN)
#define KNF (KN*KF)

// ---------------- device scratch (no allocations allowed) ----------------
__device__ float g_R[KG * KN * KF];      // [13][N][32]: R0=|x|, R1..3=|y1|, R4..12=|y2|
__device__ float g_coef[KG * KN * KF];   // [13][N][32]: U @ R
__device__ float g_h[KG * KN * KHF];     // per-branch GAT hidden [13][N][64]
__device__ float g_es[KG * KN * 2];
__device__ float g_ed[KG * KN * 2];
__device__ float g_gat[KG * KN * KHF];   // post-ELU GAT output
__device__ float g_feat[KN * KG * KNHID];// [N][832]
__device__ int   g_deg[KN];
__device__ int   g_rowptr[KN + 1];
__device__ int   g_pos[KN];
__device__ int   g_srcs[KE + KN];

// ---------------- helpers ----------------
__device__ __forceinline__ void ffma2(unsigned long long &d, unsigned long long a,
                                      unsigned long long b) {
    asm("fma.rn.f32x2 %0, %1, %2, %0;" : "+l"(d) : "l"(a), "l"(b));
}
__device__ __forceinline__ float lrelu(float v) { return v > 0.f ? v : 0.2f * v; }
__device__ __forceinline__ float eluf(float v)  { return v > 0.f ? v : expm1f(v); }

// ---------------- elementwise abs ----------------
__global__ void k_abs(const float* __restrict__ x) {
    int i = blockIdx.x * blockDim.x + threadIdx.x;
    if (i < KN * KF) g_R[i] = fabsf(x[i]);
}

// ---------------- big GEMM: C[4096,32] = A[4096,4096] @ B[4096,32] ----------------
// mode 0: A=psi_y,       B=R0,        C=R[1+y],   abs   (grid.y = 3,  HH=1)
// mode 1: A=psi_{y%3},   B=R[1+y/3],  C=R[4+y],   abs   (grid.y = 9,  HH=2)
// mode 2: A=U,           B=R[y],      C=coef[y],  noabs (grid.y = 13, HH=2)
template <int HH>
__global__ __launch_bounds__(128) void k_gemm(const float* __restrict__ ext, int mode) {
    __shared__ __align__(16) float As[32][132];   // [k][m] transposed, padded
    __shared__ float2 Bs2[32][32];                // replicated pairs

    int y = blockIdx.y;
    const float* A;
    const float* B;
    float* Cp;
    bool doAbs;
    if (mode == 0) {
        A = ext + (long long)y * KNN;  B = g_R;
        Cp = g_R + (long long)(1 + y) * KNF;  doAbs = true;
    } else if (mode == 1) {
        A = ext + (long long)(y % 3) * KNN;  B = g_R + (long long)(1 + y / 3) * KNF;
        Cp = g_R + (long long)(4 + y) * KNF;  doAbs = true;
    } else {
        A = ext;  B = g_R + (long long)y * KNF;
        Cp = g_coef + (long long)y * KNF;  doAbs = false;
    }

    int t = threadIdx.x;
    int rowBase = blockIdx.x * (64 * HH);
    int r0 = (t >> 3) << 2;   // 0..60 step 4
    int c0 = (t & 7) << 2;    // 0..28 step 4
    int lkq = t & 7;          // A-load k quad
    int lrow = t >> 3;        // 0..15

    unsigned long long acc[HH][2][4];
    #pragma unroll
    for (int h = 0; h < HH; h++)
        #pragma unroll
        for (int p = 0; p < 2; p++)
            #pragma unroll
            for (int c = 0; c < 4; c++) acc[h][p][c] = 0ULL;

    const float* Abase = A + (long long)(rowBase + lrow) * KN + lkq * 4;

    for (int k0 = 0; k0 < KN; k0 += 32) {
        // load A tile (transpose into As[k][m])
        #pragma unroll
        for (int i = 0; i < 4 * HH; i++) {
            int r = lrow + i * 16;
            float4 a4 = *(const float4*)(Abase + (long long)i * 16 * KN + k0);
            As[lkq * 4 + 0][r] = a4.x;
            As[lkq * 4 + 1][r] = a4.y;
            As[lkq * 4 + 2][r] = a4.z;
            As[lkq * 4 + 3][r] = a4.w;
        }
        // load B tile, replicate each scalar into a float2
        {
            float4 b4 = *(const float4*)(B + (long long)(k0 + lrow) * KF + c0);
            Bs2[lrow][c0 + 0] = make_float2(b4.x, b4.x);
            Bs2[lrow][c0 + 1] = make_float2(b4.y, b4.y);
            Bs2[lrow][c0 + 2] = make_float2(b4.z, b4.z);
            Bs2[lrow][c0 + 3] = make_float2(b4.w, b4.w);
            float4 b5 = *(const float4*)(B + (long long)(k0 + lrow + 16) * KF + c0);
            Bs2[lrow + 16][c0 + 0] = make_float2(b5.x, b5.x);
            Bs2[lrow + 16][c0 + 1] = make_float2(b5.y, b5.y);
            Bs2[lrow + 16][c0 + 2] = make_float2(b5.z, b5.z);
            Bs2[lrow + 16][c0 + 3] = make_float2(b5.w, b5.w);
        }
        __syncthreads();
        #pragma unroll
        for (int kk = 0; kk < 32; kk++) {
            unsigned long long a[HH][2];
            #pragma unroll
            for (int h = 0; h < HH; h++) {
                ulonglong2 av = *(const ulonglong2*)&As[kk][r0 + h * 64];
                a[h][0] = av.x;  a[h][1] = av.y;
            }
            #pragma unroll
            for (int c = 0; c < 4; c++) {
                unsigned long long bp = *(const unsigned long long*)&Bs2[kk][c0 + c];
                #pragma unroll
                for (int h = 0; h < HH; h++) {
                    ffma2(acc[h][0][c], a[h][0], bp);
                    ffma2(acc[h][1][c], a[h][1], bp);
                }
            }
        }
        __syncthreads();
    }
    #pragma unroll
    for (int h = 0; h < HH; h++)
        #pragma unroll
        for (int p = 0; p < 2; p++)
            #pragma unroll
            for (int c = 0; c < 4; c++) {
                unsigned long long v = acc[h][p][c];
                float lo = __uint_as_float((unsigned)(v & 0xffffffffULL));
                float hi = __uint_as_float((unsigned)(v >> 32));
                if (doAbs) { lo = fabsf(lo); hi = fabsf(hi); }
                int r = rowBase + h * 64 + r0 + p * 2;
                Cp[(long long)r * KF + c0 + c] = lo;
                Cp[(long long)(r + 1) * KF + c0 + c] = hi;
            }
}

// ---------------- h = coef[b] @ gat_W[b]  ([N,32]@[32,64]) ----------------
__global__ __launch_bounds__(256) void k_h(const float* __restrict__ gatW) {
    __shared__ float Ws[32 * 64];
    __shared__ float Cs[128 * 32];
    int b = blockIdx.y;
    int rowBase = blockIdx.x * 128;
    int t = threadIdx.x;
    const float* Wb = gatW + b * 32 * 64;
    const float* Cb = g_coef + (long long)b * KNF + (long long)rowBase * KF;
    for (int i = t; i < 2048; i += 256) Ws[i] = Wb[i];
    for (int i = t; i < 4096; i += 256) Cs[i] = Cb[i];
    __syncthreads();
    int col = t & 63, ns = t >> 6;
    for (int i = 0; i < 32; i++) {
        int n = i * 4 + ns;
        float acc = 0.f;
        #pragma unroll
        for (int k = 0; k < 32; k++) acc += Cs[n * 32 + k] * Ws[k * 64 + col];
        g_h[((long long)b * KN + rowBase + n) * 64 + col] = acc;
    }
}

// ---------------- attention logits es/ed ----------------
__global__ void k_esed(const float* __restrict__ att_s, const float* __restrict__ att_d) {
    int idx = blockIdx.x * blockDim.x + threadIdx.x;
    if (idx >= KG * KN) return;
    int b = idx / KN;
    const float* hr = g_h + (long long)idx * 64;
    const float* as = att_s + b * 64;
    const float* ad = att_d + b * 64;
    float e0 = 0, e1 = 0, d0 = 0, d1 = 0;
    #pragma unroll
    for (int f = 0; f < 32; f++) {
        float h0 = hr[f], h1 = hr[32 + f];
        e0 += h0 * as[f];      e1 += h1 * as[32 + f];
        d0 += h0 * ad[f];      d1 += h1 * ad[32 + f];
    }
    g_es[idx * 2] = e0;  g_es[idx * 2 + 1] = e1;
    g_ed[idx * 2] = d0;  g_ed[idx * 2 + 1] = d1;
}

// ---------------- CSR build (deterministic) ----------------
__global__ void k_zero() {
    int i = blockIdx.x * blockDim.x + threadIdx.x;
    if (i < KN) g_deg[i] = 0;
}
__global__ void k_hist(const int* __restrict__ ei) {
    int e = blockIdx.x * blockDim.x + threadIdx.x;
    if (e < KE) atomicAdd(&g_deg[ei[KE + e]], 1);
}
__global__ __launch_bounds__(1024) void k_scan() {
    __shared__ int wsum[32];
    int t = threadIdx.x;
    int base = t * 4;
    int c[4], s = 0;
    #pragma unroll
    for (int i = 0; i < 4; i++) { c[i] = g_deg[base + i] + 1; s += c[i]; }
    int lane = t & 31, wid = t >> 5;
    int v = s;
    #pragma unroll
    for (int off = 1; off < 32; off <<= 1) {
        int u = __shfl_up_sync(0xffffffffu, v, off);
        if (lane >= off) v += u;
    }
    if (lane == 31) wsum[wid] = v;
    __syncthreads();
    if (t < 32) {
        int w = wsum[t];
        #pragma unroll
        for (int off = 1; off < 32; off <<= 1) {
            int u = __shfl_up_sync(0xffffffffu, w, off);
            if (t >= off) w += u;
        }
        wsum[t] = w;
    }
    __syncthreads();
    int woff = wid ? wsum[wid - 1] : 0;
    int run = woff + v - s;   // exclusive prefix
    #pragma unroll
    for (int i = 0; i < 4; i++) {
        g_rowptr[base + i] = run;
        g_pos[base + i] = run + 1;
        g_srcs[run] = KE + base + i;   // self loop as edge-id E+n (sorts last)
        run += c[i];
    }
    if (t == 1023) g_rowptr[KN] = run;
}
__global__ void k_fill(const int* __restrict__ ei) {
    int e = blockIdx.x * blockDim.x + threadIdx.x;
    if (e < KE) {
        int d = ei[KE + e];
        int slot = atomicAdd(&g_pos[d], 1);
        g_srcs[slot] = e;
    }
}
__global__ void k_sort(const int* __restrict__ ei) {
    int n = blockIdx.x * blockDim.x + threadIdx.x;
    if (n >= KN) return;
    int beg = g_rowptr[n], end = g_rowptr[n + 1];
    for (int i = beg + 1; i < end; i++) {     // insertion sort by edge id
        int key = g_srcs[i];
        int j = i - 1;
        while (j >= beg && g_srcs[j] > key) { g_srcs[j + 1] = g_srcs[j]; j--; }
        g_srcs[j + 1] = key;
    }
    for (int i = beg; i < end; i++) {         // edge id -> src node
        int id = g_srcs[i];
        g_srcs[i] = (id < KE) ? ei[id] : (id - KE);
    }
}

// ---------------- GAT softmax + aggregation (warp per (b,dst)) ----------------
__global__ __launch_bounds__(256) void k_gat(const float* __restrict__ gatB) {
    int w = threadIdx.x >> 5, lane = threadIdx.x & 31;
    int dst = blockIdx.x * 8 + w;
    int b = blockIdx.y;
    int beg = g_rowptr[dst], end = g_rowptr[dst + 1];
    const float* es = g_es + (long long)b * KN * 2;
    const float* ed = g_ed + (long long)b * KN * 2;
    float ed0 = ed[dst * 2], ed1 = ed[dst * 2 + 1];

    float m0 = -1e30f, m1 = -1e30f;
    for (int i = beg + lane; i < end; i += 32) {
        int s = g_srcs[i];
        m0 = fmaxf(m0, lrelu(es[s * 2] + ed0));
        m1 = fmaxf(m1, lrelu(es[s * 2 + 1] + ed1));
    }
    #pragma unroll
    for (int off = 16; off; off >>= 1) {
        m0 = fmaxf(m0, __shfl_xor_sync(0xffffffffu, m0, off));
        m1 = fmaxf(m1, __shfl_xor_sync(0xffffffffu, m1, off));
    }
    float s0 = 0.f, s1 = 0.f;
    for (int i = beg + lane; i < end; i += 32) {
        int s = g_srcs[i];
        s0 += __expf(lrelu(es[s * 2] + ed0) - m0);
        s1 += __expf(lrelu(es[s * 2 + 1] + ed1) - m1);
    }
    #pragma unroll
    for (int off = 16; off; off >>= 1) {
        s0 += __shfl_xor_sync(0xffffffffu, s0, off);
        s1 += __shfl_xor_sync(0xffffffffu, s1, off);
    }
    float inv0 = 1.f / (s0 + 1e-16f), inv1 = 1.f / (s1 + 1e-16f);

    float acc0 = 0.f, acc1 = 0.f;
    for (int i = beg; i < end; i++) {
        int s = g_srcs[i];
        float a0 = __expf(lrelu(es[s * 2] + ed0) - m0) * inv0;
        float a1 = __expf(lrelu(es[s * 2 + 1] + ed1) - m1) * inv1;
        const float* hr = g_h + ((long long)b * KN + s) * 64;
        acc0 += a0 * hr[lane];
        acc1 += a1 * hr[32 + lane];
    }
    float o0 = eluf(acc0 + gatB[b * 64 + lane]);
    float o1 = eluf(acc1 + gatB[b * 64 + 32 + lane]);
    long long o = ((long long)b * KN + dst) * 64;
    g_gat[o + lane] = o0;
    g_gat[o + 32 + lane] = o1;
}

// ---------------- branch MLP: feat[n, b*64+o] = gat[b,n,:] @ mlp_W[b] + mlp_b ----------------
__global__ __launch_bounds__(256) void k_mlp(const float* __restrict__ mW,
                                             const float* __restrict__ mb) {
    __shared__ float Ws[64 * 64];
    __shared__ float Gs[64 * 64];
    int b = blockIdx.y;
    int rowBase = blockIdx.x * 64;
    int t = threadIdx.x;
    const float* Wb = mW + b * 64 * 64;
    const float* Gb = g_gat + ((long long)b * KN + rowBase) * 64;
    for (int i = t; i < 4096; i += 256) { Ws[i] = Wb[i]; Gs[i] = Gb[i]; }
    __syncthreads();
    int col = t & 63, ns = t >> 6;
    float bias = mb[b * 64 + col];
    for (int i = 0; i < 16; i++) {
        int n = i * 4 + ns;
        float acc = bias;
        #pragma unroll
        for (int k = 0; k < 64; k++) acc += Gs[n * 64 + k] * Ws[k * 64 + col];
        g_feat[(long long)(rowBase + n) * (KG * KNHID) + b * 64 + col] = acc;
    }
}

// ---------------- final head + log_softmax (warp per node) ----------------
__global__ __launch_bounds__(256) void k_final(const float* __restrict__ oW,
                                               const float* __restrict__ ob,
                                               float* __restrict__ out) {
    int w = threadIdx.x >> 5, lane = threadIdx.x & 31;
    int n = blockIdx.x * 8 + w;
    const float* fr = g_feat + (long long)n * (KG * KNHID);
    float acc[KC];
    #pragma unroll
    for (int c = 0; c < KC; c++) acc[c] = 0.f;
    for (int k = lane; k < KG * KNHID; k += 32) {
        float v = eluf(fr[k]);
        #pragma unroll
        for (int c = 0; c < KC; c++) acc[c] += v * oW[k * KC + c];
    }
    #pragma unroll
    for (int c = 0; c < KC; c++)
        #pragma unroll
        for (int off = 16; off; off >>= 1)
            acc[c] += __shfl_xor_sync(0xffffffffu, acc[c], off);
    if (lane == 0) {
        float l[KC], m = -1e30f;
        #pragma unroll
        for (int c = 0; c < KC; c++) { l[c] = acc[c] + ob[c]; m = fmaxf(m, l[c]); }
        float se = 0.f;
        #pragma unroll
        for (int c = 0; c < KC; c++) se += expf(l[c] - m);
        float lse = logf(se) + m;
        #pragma unroll
        for (int c = 0; c < KC; c++) out[(long long)n * KC + c] = l[c] - lse;
    }
}

// ---------------- launch ----------------
extern "C" void kernel_launch(void* const* d_in, const int* in_sizes, int n_in,
                              void* d_out, int out_size) {
    (void)in_sizes; (void)n_in; (void)out_size;
    const float* x     = (const float*)d_in[0];
    const int*   ei    = (const int*)d_in[1];
    const float* U     = (const float*)d_in[2];
    const float* psi   = (const float*)d_in[3];
    const float* gatW  = (const float*)d_in[4];
    const float* att_s = (const float*)d_in[5];
    const float* att_d = (const float*)d_in[6];
    const float* gatB  = (const float*)d_in[7];
    const float* mlpW  = (const float*)d_in[8];
    const float* mlpB  = (const float*)d_in[9];
    const float* outW  = (const float*)d_in[10];
    const float* outB  = (const float*)d_in[11];
    float* out = (float*)d_out;

    k_abs<<<(KN * KF + 255) / 256, 256>>>(x);

    // CSR build (independent of scattering passes)
    k_zero<<<16, 256>>>();
    k_hist<<<KE / 256, 256>>>(ei);
    k_scan<<<1, 1024>>>();
    k_fill<<<KE / 256, 256>>>(ei);
    k_sort<<<16, 256>>>(ei);

    // scattering transform: 25 big GEMMs in 3 passes
    k_gemm<1><<<dim3(64, 3), 128>>>(psi, 0);   // |psi_j @ |x||        -> R[1..3]
    k_gemm<2><<<dim3(32, 9), 128>>>(psi, 1);   // |psi_k @ R[1+j]|     -> R[4..12]
    k_gemm<2><<<dim3(32, 13), 128>>>(U, 2);    // U @ R[y]             -> coef[y]

    // 13 GAT branches
    k_h<<<dim3(32, KG), 256>>>(gatW);
    k_esed<<<(KG * KN + 255) / 256, 256>>>(att_s, att_d);
    k_gat<<<dim3(KN / 8, KG), 256>>>(gatB);
    k_mlp<<<dim3(KN / 64, KG), 256>>>(mlpW, mlpB);
    k_final<<<KN / 8, 256>>>(outW, outB, out);
}

// round 3
// speedup vs baseline: 1.4734x; 1.4734x over previous
#include <cuda_runtime.h>
#include <cuda_bf16.h>
#include <cstdint>

// Problem constants
#define KN 4096      // nodes
#define KF 32        // features
#define KHF 64       // heads*features
#define KNHID 64
#define KC 10
#define KE 65536     // edges
#define KG 13        // branches
#define KNN (KN*KN)
#define KNF (KN*KF)

// ---------------- device scratch (no allocations allowed) ----------------
__device__ __align__(128) __nv_bfloat16 g_Ah[4ull * KNN];   // psi0..2, U  (hi)
__device__ __align__(128) __nv_bfloat16 g_Al[4ull * KNN];   // (lo residual)
__device__ __align__(128) __nv_bfloat16 g_Bh[KG * KF * KN]; // B operands [slot][f][node]
__device__ __align__(128) __nv_bfloat16 g_Bl[KG * KF * KN];
__device__ float g_coef[KG * KN * KF];   // [13][N][32]: U @ R
__device__ float g_h[KG * KN * KHF];     // per-branch GAT hidden [13][N][64]
__device__ float g_es[KG * KN * 2];
__device__ float g_ed[KG * KN * 2];
__device__ float g_gat[KG * KN * KHF];   // post-ELU GAT output
__device__ float g_feat[KN * KG * KNHID];// [N][832]
__device__ int   g_deg[KN];
__device__ int   g_rowptr[KN + 1];
__device__ int   g_pos[KN];
__device__ int   g_srcs[KE + KN];

// ---------------- helpers ----------------
__device__ __forceinline__ float lrelu(float v) { return v > 0.f ? v : 0.2f * v; }
__device__ __forceinline__ float eluf(float v)  { return v > 0.f ? v : expm1f(v); }

__device__ __forceinline__ uint32_t su32(const void* p) {
    return (uint32_t)__cvta_generic_to_shared(p);
}
__device__ __forceinline__ void cpa16(uint32_t dst, const void* src) {
    asm volatile("cp.async.cg.shared.global [%0], [%1], 16;" :: "r"(dst), "l"(src) : "memory");
}
__device__ __forceinline__ uint32_t swz(uint32_t off) { return off ^ ((off >> 3) & 0x70); }

#define LDSM4(d, addr) \
    asm volatile("ldmatrix.sync.aligned.m8n8.x4.shared.b16 {%0,%1,%2,%3}, [%4];" \
        : "=r"((d)[0]), "=r"((d)[1]), "=r"((d)[2]), "=r"((d)[3]) : "r"(addr))

__device__ __forceinline__ void mma_bf16(float* c, const uint32_t* a,
                                         uint32_t b0, uint32_t b1) {
    asm volatile("mma.sync.aligned.m16n8k16.row.col.f32.bf16.bf16.f32 "
        "{%0,%1,%2,%3}, {%4,%5,%6,%7}, {%8,%9}, {%0,%1,%2,%3};"
        : "+f"(c[0]), "+f"(c[1]), "+f"(c[2]), "+f"(c[3])
        : "r"(a[0]), "r"(a[1]), "r"(a[2]), "r"(a[3]), "r"(b0), "r"(b1));
}

// ---------------- |x| -> transposed bf16 split (B slot 0) ----------------
__global__ void k_absT(const float* __restrict__ x) {
    int i = blockIdx.x * 256 + threadIdx.x;
    if (i >= KN * KF) return;
    int node = i >> 5, f = i & 31;
    float v = fabsf(x[i]);
    __nv_bfloat16 h = __float2bfloat16(v);
    g_Bh[f * KN + node] = h;
    g_Bl[f * KN + node] = __float2bfloat16(v - __bfloat162float(h));
}

// ---------------- psi/U fp32 -> bf16 hi/lo ----------------
__global__ __launch_bounds__(256) void k_convA(const float* __restrict__ U,
                                               const float* __restrict__ psi) {
    size_t i = ((size_t)blockIdx.x * 256 + threadIdx.x) * 4;
    if (i >= 4ull * KNN) return;
    float4 v = (i < 3ull * KNN) ? *(const float4*)(psi + i)
                                : *(const float4*)(U + (i - 3ull * KNN));
    __nv_bfloat16 h0 = __float2bfloat16(v.x), h1 = __float2bfloat16(v.y);
    __nv_bfloat16 h2 = __float2bfloat16(v.z), h3 = __float2bfloat16(v.w);
    __nv_bfloat162* ph = (__nv_bfloat162*)(g_Ah + i);
    ph[0] = __nv_bfloat162(h0, h1);  ph[1] = __nv_bfloat162(h2, h3);
    __nv_bfloat162* pl = (__nv_bfloat162*)(g_Al + i);
    pl[0] = __nv_bfloat162(__float2bfloat16(v.x - __bfloat162float(h0)),
                           __float2bfloat16(v.y - __bfloat162float(h1)));
    pl[1] = __nv_bfloat162(__float2bfloat16(v.z - __bfloat162float(h2)),
                           __float2bfloat16(v.w - __bfloat162float(h3)));
}

// ---------------- mma.sync scattering GEMM ----------------
// C[128-tile, nb*32] = A[128, 4096] @ B^T, 3-part bf16 split, K-chunks of 64.
// mode 0: A=psi_y,  B={slot0},  out {1+y},           abs-split
// mode 1: A=psi_y,  B={1,2,3},  out {4+3b+y},        abs-split
// mode 2: A=U, group y: slots {st..st+nb-1}, st=(y?1+3y:0), nb=(y?3:4), coef fp32
template <int NBMAX>
__global__ __launch_bounds__(256) void k_mma(int mode) {
    extern __shared__ char dsm[];
    int tid = threadIdx.x;
    uint32_t sbase = (su32(dsm) + 1023u) & ~1023u;

    int y = blockIdx.y;
    int rowBase = blockIdx.x * 128;
    int nb;
    int slotIn[NBMAX], slotOut[NBMAX];
    const __nv_bfloat16* Ah;
    bool absOut;
    if (mode == 0) {
        nb = 1; Ah = g_Ah + (size_t)y * KNN; slotIn[0] = 0; slotOut[0] = 1 + y; absOut = true;
    } else if (mode == 1) {
        nb = 3; Ah = g_Ah + (size_t)y * KNN;
        #pragma unroll
        for (int j = 0; j < NBMAX; j++) { slotIn[j] = 1 + j; slotOut[j] = 4 + j * 3 + y; }
        absOut = true;
    } else {
        nb = (y == 0) ? 4 : 3;
        int st = (y == 0) ? 0 : (1 + 3 * y);
        #pragma unroll
        for (int b = 0; b < NBMAX; b++) { slotIn[b] = st + b; slotOut[b] = st + b; }
        absOut = false; Ah = g_Ah + (size_t)3 * KNN;
    }
    const __nv_bfloat16* Al = g_Al + (Ah - g_Ah);

    // smem: A(stage,part) 16KB each (6), then B(stage,part,b) 4KB each
    auto A_at = [&](int st, int p) { return sbase + (uint32_t)(st * 2 + p) * 16384u; };
    auto B_at = [&](int st, int p, int b) {
        return sbase + 98304u + (uint32_t)((st * 2 + p) * NBMAX + b) * 4096u;
    };

    auto ldChunk = [&](int c, int s) {
        int k0 = c * 64;
        #pragma unroll
        for (int i0 = 0; i0 < 4; i0++) {   // A: 1024 16B segs x 2 parts
            int i = i0 * 256 + tid;
            int r = i >> 3, seg = i & 7;
            uint32_t sw = swz((uint32_t)(r * 128 + seg * 16));
            size_t go = (size_t)(rowBase + r) * KN + k0 + seg * 8;
            cpa16(A_at(s, 0) + sw, Ah + go);
            cpa16(A_at(s, 1) + sw, Al + go);
        }
        for (int b = 0; b < nb; b++) {     // B: 256 segs x 2 parts per branch
            int r = tid >> 3, seg = tid & 7;
            uint32_t sw = swz((uint32_t)(r * 128 + seg * 16));
            size_t go = (size_t)slotIn[b] * (KF * KN) + (size_t)r * KN + k0 + seg * 8;
            cpa16(B_at(s, 0, b) + sw, g_Bh + go);
            cpa16(B_at(s, 1, b) + sw, g_Bl + go);
        }
    };

    int wid = tid >> 5, lane = tid & 31;
    // ldmatrix lane addresses (byte offsets within a tile, swizzled per use)
    auto aAddr = [&](uint32_t base, int q) {
        int row = (wid << 4) + (lane & 15);
        int col = q * 32 + ((lane >> 4) << 4);
        return base + swz((uint32_t)(row * 128 + col));
    };
    auto bAddr = [&](uint32_t base, int n0, int q) {
        int j = lane >> 3, r = lane & 7;
        int row = n0 + ((j >> 1) << 3) + r;
        int col = q * 32 + ((j & 1) << 4);
        return base + swz((uint32_t)(row * 128 + col));
    };

    float acc[NBMAX][16];
    #pragma unroll
    for (int b = 0; b < NBMAX; b++)
        #pragma unroll
        for (int i = 0; i < 16; i++) acc[b][i] = 0.f;

    ldChunk(0, 0);
    asm volatile("cp.async.commit_group;" ::: "memory");
    ldChunk(1, 1);
    asm volatile("cp.async.commit_group;" ::: "memory");
    ldChunk(2, 2);
    asm volatile("cp.async.commit_group;" ::: "memory");

    const int NCH = KN / 64;   // 64 chunks
    for (int i = 0; i < NCH; i++) {
        int s = i % 3;
        asm volatile("cp.async.wait_group 2;" ::: "memory");
        __syncthreads();
        #pragma unroll
        for (int q = 0; q < 4; q++) {
            uint32_t ah[4], al[4];
            LDSM4(ah, aAddr(A_at(s, 0), q));
            LDSM4(al, aAddr(A_at(s, 1), q));
            for (int b = 0; b < nb; b++) {
                uint32_t bh[8], bl[8];
                LDSM4(&bh[0], bAddr(B_at(s, 0, b), 0, q));
                LDSM4(&bh[4], bAddr(B_at(s, 0, b), 16, q));
                LDSM4(&bl[0], bAddr(B_at(s, 1, b), 0, q));
                LDSM4(&bl[4], bAddr(B_at(s, 1, b), 16, q));
                #pragma unroll
                for (int nt = 0; nt < 4; nt++) {
                    float* c = acc[b] + nt * 4;
                    mma_bf16(c, ah, bh[2 * nt], bh[2 * nt + 1]);
                    mma_bf16(c, ah, bl[2 * nt], bl[2 * nt + 1]);
                    mma_bf16(c, al, bh[2 * nt], bh[2 * nt + 1]);
                }
            }
        }
        __syncthreads();
        if (i + 3 < NCH) ldChunk(i + 3, s);
        asm volatile("cp.async.commit_group;" ::: "memory");
    }

    // epilogue: write accumulators
    int quad = lane >> 2, tq = lane & 3;
    int nodeLo = rowBase + wid * 16 + quad;
    for (int b = 0; b < nb; b++) {
        #pragma unroll
        for (int nt = 0; nt < 4; nt++) {
            float* c = acc[b] + nt * 4;
            int f0 = nt * 8 + tq * 2;
            if (absOut) {
                size_t sb = (size_t)slotOut[b] * (KF * KN);
                #pragma unroll
                for (int e = 0; e < 4; e++) {
                    int node = nodeLo + ((e >> 1) << 3);
                    int f = f0 + (e & 1);
                    float v = fabsf(c[e]);
                    __nv_bfloat16 h = __float2bfloat16(v);
                    size_t o = sb + (size_t)f * KN + node;
                    g_Bh[o] = h;
                    g_Bl[o] = __float2bfloat16(v - __bfloat162float(h));
                }
            } else {
                size_t sb = (size_t)slotOut[b] * KN;
                #pragma unroll
                for (int e = 0; e < 4; e++) {
                    int node = nodeLo + ((e >> 1) << 3);
                    int f = f0 + (e & 1);
                    g_coef[(sb + node) * KF + f] = c[e];
                }
            }
        }
    }
}

// ---------------- h = coef[b] @ gat_W[b]  ([N,32]@[32,64]) ----------------
__global__ __launch_bounds__(256) void k_h(const float* __restrict__ gatW) {
    __shared__ float Ws[32 * 64];
    __shared__ float Cs[128 * 32];
    int b = blockIdx.y;
    int rowBase = blockIdx.x * 128;
    int t = threadIdx.x;
    const float* Wb = gatW + b * 32 * 64;
    const float* Cb = g_coef + (long long)b * KNF + (long long)rowBase * KF;
    for (int i = t; i < 2048; i += 256) Ws[i] = Wb[i];
    for (int i = t; i < 4096; i += 256) Cs[i] = Cb[i];
    __syncthreads();
    int col = t & 63, ns = t >> 6;
    for (int i = 0; i < 32; i++) {
        int n = i * 4 + ns;
        float acc = 0.f;
        #pragma unroll
        for (int k = 0; k < 32; k++) acc += Cs[n * 32 + k] * Ws[k * 64 + col];
        g_h[((long long)b * KN + rowBase + n) * 64 + col] = acc;
    }
}

// ---------------- attention logits es/ed ----------------
__global__ void k_esed(const float* __restrict__ att_s, const float* __restrict__ att_d) {
    int idx = blockIdx.x * blockDim.x + threadIdx.x;
    if (idx >= KG * KN) return;
    int b = idx / KN;
    const float* hr = g_h + (long long)idx * 64;
    const float* as = att_s + b * 64;
    const float* ad = att_d + b * 64;
    float e0 = 0, e1 = 0, d0 = 0, d1 = 0;
    #pragma unroll
    for (int f = 0; f < 32; f++) {
        float h0 = hr[f], h1 = hr[32 + f];
        e0 += h0 * as[f];      e1 += h1 * as[32 + f];
        d0 += h0 * ad[f];      d1 += h1 * ad[32 + f];
    }
    g_es[idx * 2] = e0;  g_es[idx * 2 + 1] = e1;
    g_ed[idx * 2] = d0;  g_ed[idx * 2 + 1] = d1;
}

// ---------------- CSR build (deterministic) ----------------
__global__ void k_zero() {
    int i = blockIdx.x * blockDim.x + threadIdx.x;
    if (i < KN) g_deg[i] = 0;
}
__global__ void k_hist(const int* __restrict__ ei) {
    int e = blockIdx.x * blockDim.x + threadIdx.x;
    if (e < KE) atomicAdd(&g_deg[ei[KE + e]], 1);
}
__global__ __launch_bounds__(1024) void k_scan() {
    __shared__ int wsum[32];
    int t = threadIdx.x;
    int base = t * 4;
    int c[4], s = 0;
    #pragma unroll
    for (int i = 0; i < 4; i++) { c[i] = g_deg[base + i] + 1; s += c[i]; }
    int lane = t & 31, wid = t >> 5;
    int v = s;
    #pragma unroll
    for (int off = 1; off < 32; off <<= 1) {
        int u = __shfl_up_sync(0xffffffffu, v, off);
        if (lane >= off) v += u;
    }
    if (lane == 31) wsum[wid] = v;
    __syncthreads();
    if (t < 32) {
        int w = wsum[t];
        #pragma unroll
        for (int off = 1; off < 32; off <<= 1) {
            int u = __shfl_up_sync(0xffffffffu, w, off);
            if (t >= off) w += u;
        }
        wsum[t] = w;
    }
    __syncthreads();
    int woff = wid ? wsum[wid - 1] : 0;
    int run = woff + v - s;   // exclusive prefix
    #pragma unroll
    for (int i = 0; i < 4; i++) {
        g_rowptr[base + i] = run;
        g_pos[base + i] = run + 1;
        g_srcs[run] = KE + base + i;   // self loop as edge-id E+n (sorts last)
        run += c[i];
    }
    if (t == 1023) g_rowptr[KN] = run;
}
__global__ void k_fill(const int* __restrict__ ei) {
    int e = blockIdx.x * blockDim.x + threadIdx.x;
    if (e < KE) {
        int d = ei[KE + e];
        int slot = atomicAdd(&g_pos[d], 1);
        g_srcs[slot] = e;
    }
}
__global__ void k_sort(const int* __restrict__ ei) {
    int n = blockIdx.x * blockDim.x + threadIdx.x;
    if (n >= KN) return;
    int beg = g_rowptr[n], end = g_rowptr[n + 1];
    for (int i = beg + 1; i < end; i++) {     // insertion sort by edge id
        int key = g_srcs[i];
        int j = i - 1;
        while (j >= beg && g_srcs[j] > key) { g_srcs[j + 1] = g_srcs[j]; j--; }
        g_srcs[j + 1] = key;
    }
    for (int i = beg; i < end; i++) {         // edge id -> src node
        int id = g_srcs[i];
        g_srcs[i] = (id < KE) ? ei[id] : (id - KE);
    }
}

// ---------------- GAT softmax + aggregation (warp per (b,dst)) ----------------
__global__ __launch_bounds__(256) void k_gat(const float* __restrict__ gatB) {
    int w = threadIdx.x >> 5, lane = threadIdx.x & 31;
    int dst = blockIdx.x * 8 + w;
    int b = blockIdx.y;
    int beg = g_rowptr[dst], end = g_rowptr[dst + 1];
    const float* es = g_es + (long long)b * KN * 2;
    const float* ed = g_ed + (long long)b * KN * 2;
    float ed0 = ed[dst * 2], ed1 = ed[dst * 2 + 1];

    float m0 = -1e30f, m1 = -1e30f;
    for (int i = beg + lane; i < end; i += 32) {
        int s = g_srcs[i];
        m0 = fmaxf(m0, lrelu(es[s * 2] + ed0));
        m1 = fmaxf(m1, lrelu(es[s * 2 + 1] + ed1));
    }
    #pragma unroll
    for (int off = 16; off; off >>= 1) {
        m0 = fmaxf(m0, __shfl_xor_sync(0xffffffffu, m0, off));
        m1 = fmaxf(m1, __shfl_xor_sync(0xffffffffu, m1, off));
    }
    float s0 = 0.f, s1 = 0.f;
    for (int i = beg + lane; i < end; i += 32) {
        int s = g_srcs[i];
        s0 += __expf(lrelu(es[s * 2] + ed0) - m0);
        s1 += __expf(lrelu(es[s * 2 + 1] + ed1) - m1);
    }
    #pragma unroll
    for (int off = 16; off; off >>= 1) {
        s0 += __shfl_xor_sync(0xffffffffu, s0, off);
        s1 += __shfl_xor_sync(0xffffffffu, s1, off);
    }
    float inv0 = 1.f / (s0 + 1e-16f), inv1 = 1.f / (s1 + 1e-16f);

    float acc0 = 0.f, acc1 = 0.f;
    for (int i = beg; i < end; i++) {
        int s = g_srcs[i];
        float a0 = __expf(lrelu(es[s * 2] + ed0) - m0) * inv0;
        float a1 = __expf(lrelu(es[s * 2 + 1] + ed1) - m1) * inv1;
        const float* hr = g_h + ((long long)b * KN + s) * 64;
        acc0 += a0 * hr[lane];
        acc1 += a1 * hr[32 + lane];
    }
    float o0 = eluf(acc0 + gatB[b * 64 + lane]);
    float o1 = eluf(acc1 + gatB[b * 64 + 32 + lane]);
    long long o = ((long long)b * KN + dst) * 64;
    g_gat[o + lane] = o0;
    g_gat[o + 32 + lane] = o1;
}

// ---------------- branch MLP ----------------
__global__ __launch_bounds__(256) void k_mlp(const float* __restrict__ mW,
                                             const float* __restrict__ mb) {
    __shared__ float Ws[64 * 64];
    __shared__ float Gs[64 * 64];
    int b = blockIdx.y;
    int rowBase = blockIdx.x * 64;
    int t = threadIdx.x;
    const float* Wb = mW + b * 64 * 64;
    const float* Gb = g_gat + ((long long)b * KN + rowBase) * 64;
    for (int i = t; i < 4096; i += 256) { Ws[i] = Wb[i]; Gs[i] = Gb[i]; }
    __syncthreads();
    int col = t & 63, ns = t >> 6;
    float bias = mb[b * 64 + col];
    for (int i = 0; i < 16; i++) {
        int n = i * 4 + ns;
        float acc = bias;
        #pragma unroll
        for (int k = 0; k < 64; k++) acc += Gs[n * 64 + k] * Ws[k * 64 + col];
        g_feat[(long long)(rowBase + n) * (KG * KNHID) + b * 64 + col] = acc;
    }
}

// ---------------- final head + log_softmax (warp per node) ----------------
__global__ __launch_bounds__(256) void k_final(const float* __restrict__ oW,
                                               const float* __restrict__ ob,
                                               float* __restrict__ out) {
    int w = threadIdx.x >> 5, lane = threadIdx.x & 31;
    int n = blockIdx.x * 8 + w;
    const float* fr = g_feat + (long long)n * (KG * KNHID);
    float acc[KC];
    #pragma unroll
    for (int c = 0; c < KC; c++) acc[c] = 0.f;
    for (int k = lane; k < KG * KNHID; k += 32) {
        float v = eluf(fr[k]);
        #pragma unroll
        for (int c = 0; c < KC; c++) acc[c] += v * oW[k * KC + c];
    }
    #pragma unroll
    for (int c = 0; c < KC; c++)
        #pragma unroll
        for (int off = 16; off; off >>= 1)
            acc[c] += __shfl_xor_sync(0xffffffffu, acc[c], off);
    if (lane == 0) {
        float l[KC], m = -1e30f;
        #pragma unroll
        for (int c = 0; c < KC; c++) { l[c] = acc[c] + ob[c]; m = fmaxf(m, l[c]); }
        float se = 0.f;
        #pragma unroll
        for (int c = 0; c < KC; c++) se += expf(l[c] - m);
        float lse = logf(se) + m;
        #pragma unroll
        for (int c = 0; c < KC; c++) out[(long long)n * KC + c] = l[c] - lse;
    }
}

// ---------------- launch ----------------
static inline int smemBytes(int nbmax) { return 1024 + 98304 + nbmax * 6 * 4096; }

extern "C" void kernel_launch(void* const* d_in, const int* in_sizes, int n_in,
                              void* d_out, int out_size) {
    (void)in_sizes; (void)n_in; (void)out_size;
    const float* x     = (const float*)d_in[0];
    const int*   ei    = (const int*)d_in[1];
    const float* U     = (const float*)d_in[2];
    const float* psi   = (const float*)d_in[3];
    const float* gatW  = (const float*)d_in[4];
    const float* att_s = (const float*)d_in[5];
    const float* att_d = (const float*)d_in[6];
    const float* gatB  = (const float*)d_in[7];
    const float* mlpW  = (const float*)d_in[8];
    const float* mlpB  = (const float*)d_in[9];
    const float* outW  = (const float*)d_in[10];
    const float* outB  = (const float*)d_in[11];
    float* out = (float*)d_out;

    cudaFuncSetAttribute(k_mma<1>, cudaFuncAttributeMaxDynamicSharedMemorySize, smemBytes(1));
    cudaFuncSetAttribute(k_mma<3>, cudaFuncAttributeMaxDynamicSharedMemorySize, smemBytes(3));
    cudaFuncSetAttribute(k_mma<4>, cudaFuncAttributeMaxDynamicSharedMemorySize, smemBytes(4));

    k_absT<<<(KN * KF + 255) / 256, 256>>>(x);
    k_convA<<<(int)((4ull * KNN / 4 + 255) / 256), 256>>>(U, psi);

    // scattering transform on tensor cores (mma.sync / HMMA)
    k_mma<1><<<dim3(32, 3), 256, smemBytes(1)>>>(0);
    k_mma<3><<<dim3(32, 3), 256, smemBytes(3)>>>(1);
    k_mma<4><<<dim3(32, 4), 256, smemBytes(4)>>>(2);

    // CSR build
    k_zero<<<16, 256>>>();
    k_hist<<<KE / 256, 256>>>(ei);
    k_scan<<<1, 1024>>>();
    k_fill<<<KE / 256, 256>>>(ei);
    k_sort<<<16, 256>>>(ei);

    // 13 GAT branches
    k_h<<<dim3(32, KG), 256>>>(gatW);
    k_esed<<<(KG * KN + 255) / 256, 256>>>(att_s, att_d);
    k_gat<<<dim3(KN / 8, KG), 256>>>(gatB);
    k_mlp<<<dim3(KN / 64, KG), 256>>>(mlpW, mlpB);
    k_final<<<KN / 8, 256>>>(outW, outB, out);
}

// round 4
// speedup vs baseline: 1.8532x; 1.2577x over previous
#include <cuda_runtime.h>
#include <cuda_bf16.h>
#include <cstdint>

// Problem constants
#define KN 4096      // nodes
#define KF 32        // features
#define KHF 64       // heads*features
#define KNHID 64
#define KC 10
#define KE 65536     // edges
#define KG 13        // branches
#define KNN (KN*KN)
#define KNF (KN*KF)

// ---------------- device scratch (no allocations allowed) ----------------
__device__ __align__(128) __nv_bfloat16 g_Ah[4ull * KNN];   // psi0..2, U  (hi)
__device__ __align__(128) __nv_bfloat16 g_Al[4ull * KNN];   // (lo residual)
__device__ __align__(128) __nv_bfloat16 g_Bh[KG * KF * KN]; // B operands [slot][f][node]
__device__ __align__(128) __nv_bfloat16 g_Bl[KG * KF * KN];
__device__ float g_coef[KG * KN * KF];   // [13][N][32]: U @ R
__device__ float g_h[KG * KN * KHF];     // per-branch GAT hidden [13][N][64]
__device__ float g_es[KG * KN * 2];
__device__ float g_ed[KG * KN * 2];
__device__ float g_gat[KG * KN * KHF];   // post-ELU GAT output
__device__ float g_feat[KN * KG * KNHID];// [N][832]
__device__ int   g_deg[KN];
__device__ int   g_rowptr[KN + 1];
__device__ int   g_pos[KN];
__device__ int   g_srcs[KE + KN];

// ---------------- helpers ----------------
__device__ __forceinline__ float lrelu(float v) { return v > 0.f ? v : 0.2f * v; }
__device__ __forceinline__ float eluf(float v)  { return v > 0.f ? v : expm1f(v); }

__device__ __forceinline__ uint32_t su32(const void* p) {
    return (uint32_t)__cvta_generic_to_shared(p);
}
__device__ __forceinline__ void cpa16(uint32_t dst, const void* src) {
    asm volatile("cp.async.cg.shared.global [%0], [%1], 16;" :: "r"(dst), "l"(src) : "memory");
}
__device__ __forceinline__ uint32_t swz(uint32_t off) { return off ^ ((off >> 3) & 0x70); }

#define LDSM4(d, addr) \
    asm volatile("ldmatrix.sync.aligned.m8n8.x4.shared.b16 {%0,%1,%2,%3}, [%4];" \
        : "=r"((d)[0]), "=r"((d)[1]), "=r"((d)[2]), "=r"((d)[3]) : "r"(addr))

__device__ __forceinline__ void mma_bf16(float* c, const uint32_t* a,
                                         uint32_t b0, uint32_t b1) {
    asm volatile("mma.sync.aligned.m16n8k16.row.col.f32.bf16.bf16.f32 "
        "{%0,%1,%2,%3}, {%4,%5,%6,%7}, {%8,%9}, {%0,%1,%2,%3};"
        : "+f"(c[0]), "+f"(c[1]), "+f"(c[2]), "+f"(c[3])
        : "r"(a[0]), "r"(a[1]), "r"(a[2]), "r"(a[3]), "r"(b0), "r"(b1));
}

// ---------------- |x| -> transposed bf16 split (B slot 0) ----------------
__global__ void k_absT(const float* __restrict__ x) {
    int i = blockIdx.x * 256 + threadIdx.x;
    if (i >= KN * KF) return;
    int node = i >> 5, f = i & 31;
    float v = fabsf(x[i]);
    __nv_bfloat16 h = __float2bfloat16(v);
    g_Bh[f * KN + node] = h;
    g_Bl[f * KN + node] = __float2bfloat16(v - __bfloat162float(h));
}

// ---------------- psi/U fp32 -> bf16 hi/lo ----------------
__global__ __launch_bounds__(256) void k_convA(const float* __restrict__ U,
                                               const float* __restrict__ psi) {
    size_t i = ((size_t)blockIdx.x * 256 + threadIdx.x) * 4;
    if (i >= 4ull * KNN) return;
    float4 v = (i < 3ull * KNN) ? *(const float4*)(psi + i)
                                : *(const float4*)(U + (i - 3ull * KNN));
    __nv_bfloat16 h0 = __float2bfloat16(v.x), h1 = __float2bfloat16(v.y);
    __nv_bfloat16 h2 = __float2bfloat16(v.z), h3 = __float2bfloat16(v.w);
    __nv_bfloat162* ph = (__nv_bfloat162*)(g_Ah + i);
    ph[0] = __nv_bfloat162(h0, h1);  ph[1] = __nv_bfloat162(h2, h3);
    __nv_bfloat162* pl = (__nv_bfloat162*)(g_Al + i);
    pl[0] = __nv_bfloat162(__float2bfloat16(v.x - __bfloat162float(h0)),
                           __float2bfloat16(v.y - __bfloat162float(h1)));
    pl[1] = __nv_bfloat162(__float2bfloat16(v.z - __bfloat162float(h2)),
                           __float2bfloat16(v.w - __bfloat162float(h3)));
}

// ---------------- mma.sync scattering GEMM ----------------
// C[128-tile, NB*32] = A[128, 4096] @ B^T, 3-part bf16 split, K-chunks of 64.
// 8 warps = 4(M) x 2(N); warp tile m32 x (NB*16). 2-stage cp.async pipeline.
// NB=1 launches: mode0 (psi_y, in 0, out 1+y), mode1b (psi_y, in 3, out 10+y),
//                mode2b (U, slot 12)
// NB=2 launches: mode1a (psi_y, in {1,2}, out {4+y,7+y}),
//                mode2a (U, slots {2y, 2y+1})
template <int NB>
__global__ __launch_bounds__(256, 2) void k_mma(int mode) {
    extern __shared__ char dsm[];
    int tid = threadIdx.x;
    uint32_t sbase = (su32(dsm) + 1023u) & ~1023u;

    int y = blockIdx.y;
    int rowBase = blockIdx.x * 128;
    int slotIn[NB], slotOut[NB];
    const __nv_bfloat16* Ah;
    bool absOut;
    if (NB == 1) {
        if (mode == 0)      { Ah = g_Ah + (size_t)y * KNN; slotIn[0] = 0;  slotOut[0] = 1 + y;  absOut = true; }
        else if (mode == 1) { Ah = g_Ah + (size_t)y * KNN; slotIn[0] = 3;  slotOut[0] = 10 + y; absOut = true; }
        else                { Ah = g_Ah + (size_t)3 * KNN; slotIn[0] = 12; slotOut[0] = 12;     absOut = false; }
    } else {
        if (mode == 1) {
            Ah = g_Ah + (size_t)y * KNN;
            slotIn[0] = 1; slotIn[1] = 2;
            slotOut[0] = 4 + y; slotOut[1] = 7 + y;
            absOut = true;
        } else {
            Ah = g_Ah + (size_t)3 * KNN;
            slotIn[0] = 2 * y; slotIn[1] = 2 * y + 1;
            slotOut[0] = 2 * y; slotOut[1] = 2 * y + 1;
            absOut = false;
        }
    }
    const __nv_bfloat16* Al = g_Al + (Ah - g_Ah);

    // smem: A(stage,part) 16KB x4, then B(stage,part,b) 4KB each
    auto A_at = [&](int st, int p) { return sbase + (uint32_t)(st * 2 + p) * 16384u; };
    auto B_at = [&](int st, int p, int b) {
        return sbase + 65536u + (uint32_t)((st * 2 + p) * NB + b) * 4096u;
    };

    auto ldChunk = [&](int c, int s) {
        int k0 = c * 64;
        #pragma unroll
        for (int i0 = 0; i0 < 4; i0++) {   // A: 1024 16B segs x 2 parts
            int i = i0 * 256 + tid;
            int r = i >> 3, seg = i & 7;
            uint32_t sw = swz((uint32_t)(r * 128 + seg * 16));
            size_t go = (size_t)(rowBase + r) * KN + k0 + seg * 8;
            cpa16(A_at(s, 0) + sw, Ah + go);
            cpa16(A_at(s, 1) + sw, Al + go);
        }
        #pragma unroll
        for (int b = 0; b < NB; b++) {     // B: 256 16B segs x 2 parts per branch
            int r = tid >> 3, seg = tid & 7;
            uint32_t sw = swz((uint32_t)(r * 128 + seg * 16));
            size_t go = (size_t)slotIn[b] * (KF * KN) + (size_t)r * KN + k0 + seg * 8;
            cpa16(B_at(s, 0, b) + sw, g_Bh + go);
            cpa16(B_at(s, 1, b) + sw, g_Bl + go);
        }
    };

    int wid = tid >> 5, lane = tid & 31;
    int wm = wid >> 1, wn = wid & 1;       // 4 M-warps x 2 N-warps

    // ldmatrix addresses (within swizzled 128B-row tiles)
    auto aAddr = [&](uint32_t base, int mt, int q) {
        int row = wm * 32 + mt * 16 + (lane & 15);
        int col = q * 32 + ((lane >> 4) << 4);
        return base + swz((uint32_t)(row * 128 + col));
    };
    auto bAddr = [&](uint32_t base, int n0, int q) {
        int j = lane >> 3, r = lane & 7;
        int row = n0 + ((j >> 1) << 3) + r;
        int col = q * 32 + ((j & 1) << 4);
        return base + swz((uint32_t)(row * 128 + col));
    };

    float acc[2][2 * NB][4];
    #pragma unroll
    for (int mt = 0; mt < 2; mt++)
        #pragma unroll
        for (int n = 0; n < 2 * NB; n++)
            #pragma unroll
            for (int e = 0; e < 4; e++) acc[mt][n][e] = 0.f;

    ldChunk(0, 0);
    asm volatile("cp.async.commit_group;" ::: "memory");

    const int NCH = KN / 64;   // 64 chunks
    for (int i = 0; i < NCH; i++) {
        int s = i & 1;
        asm volatile("cp.async.wait_group 0;" ::: "memory");
        __syncthreads();
        if (i + 1 < NCH) ldChunk(i + 1, (i + 1) & 1);
        asm volatile("cp.async.commit_group;" ::: "memory");

        #pragma unroll
        for (int q = 0; q < 4; q++) {      // k16 steps
            uint32_t ah[2][4], al[2][4];
            #pragma unroll
            for (int mt = 0; mt < 2; mt++) {
                LDSM4(ah[mt], aAddr(A_at(s, 0), mt, q));
                LDSM4(al[mt], aAddr(A_at(s, 1), mt, q));
            }
            #pragma unroll
            for (int t16 = 0; t16 < NB; t16++) {
                int g16 = wn * NB + t16;
                int b = g16 >> 1, n0 = (g16 & 1) * 16;
                uint32_t bh[4], bl[4];
                LDSM4(bh, bAddr(B_at(s, 0, b), n0, q));
                LDSM4(bl, bAddr(B_at(s, 1, b), n0, q));
                #pragma unroll
                for (int n8 = 0; n8 < 2; n8++) {
                    uint32_t h0 = bh[2 * n8], h1 = bh[2 * n8 + 1];
                    uint32_t l0 = bl[2 * n8], l1 = bl[2 * n8 + 1];
                    #pragma unroll
                    for (int mt = 0; mt < 2; mt++) {
                        float* c = acc[mt][t16 * 2 + n8];
                        mma_bf16(c, ah[mt], h0, h1);
                        mma_bf16(c, ah[mt], l0, l1);
                        mma_bf16(c, al[mt], h0, h1);
                    }
                }
            }
        }
    }

    // epilogue
    int quad = lane >> 2, tq = lane & 3;
    #pragma unroll
    for (int mt = 0; mt < 2; mt++) {
        int rBase = rowBase + wm * 32 + mt * 16 + quad;
        #pragma unroll
        for (int t16 = 0; t16 < NB; t16++) {
            int g16 = wn * NB + t16;
            int b = g16 >> 1;
            #pragma unroll
            for (int n8 = 0; n8 < 2; n8++) {
                float* c = acc[mt][t16 * 2 + n8];
                int f0 = (g16 & 1) * 16 + n8 * 8 + tq * 2;
                if (absOut) {
                    size_t sb = (size_t)slotOut[b] * (KF * KN);
                    #pragma unroll
                    for (int e = 0; e < 4; e++) {
                        int row = rBase + ((e >> 1) << 3);
                        int f = f0 + (e & 1);
                        float v = fabsf(c[e]);
                        __nv_bfloat16 h = __float2bfloat16(v);
                        size_t o = sb + (size_t)f * KN + row;
                        g_Bh[o] = h;
                        g_Bl[o] = __float2bfloat16(v - __bfloat162float(h));
                    }
                } else {
                    size_t sb = (size_t)slotOut[b] * KN;
                    #pragma unroll
                    for (int e = 0; e < 4; e++) {
                        int row = rBase + ((e >> 1) << 3);
                        int f = f0 + (e & 1);
                        g_coef[(sb + row) * KF + f] = c[e];
                    }
                }
            }
        }
    }
}

// ---------------- h = coef[b] @ gat_W[b]  ([N,32]@[32,64]) ----------------
__global__ __launch_bounds__(256) void k_h(const float* __restrict__ gatW) {
    __shared__ float Ws[32 * 64];
    __shared__ float Cs[128 * 32];
    int b = blockIdx.y;
    int rowBase = blockIdx.x * 128;
    int t = threadIdx.x;
    const float* Wb = gatW + b * 32 * 64;
    const float* Cb = g_coef + (long long)b * KNF + (long long)rowBase * KF;
    for (int i = t; i < 2048; i += 256) Ws[i] = Wb[i];
    for (int i = t; i < 4096; i += 256) Cs[i] = Cb[i];
    __syncthreads();
    int col = t & 63, ns = t >> 6;
    for (int i = 0; i < 32; i++) {
        int n = i * 4 + ns;
        float acc = 0.f;
        #pragma unroll
        for (int k = 0; k < 32; k++) acc += Cs[n * 32 + k] * Ws[k * 64 + col];
        g_h[((long long)b * KN + rowBase + n) * 64 + col] = acc;
    }
}

// ---------------- attention logits es/ed ----------------
__global__ void k_esed(const float* __restrict__ att_s, const float* __restrict__ att_d) {
    int idx = blockIdx.x * blockDim.x + threadIdx.x;
    if (idx >= KG * KN) return;
    int b = idx / KN;
    const float* hr = g_h + (long long)idx * 64;
    const float* as = att_s + b * 64;
    const float* ad = att_d + b * 64;
    float e0 = 0, e1 = 0, d0 = 0, d1 = 0;
    #pragma unroll
    for (int f = 0; f < 32; f++) {
        float h0 = hr[f], h1 = hr[32 + f];
        e0 += h0 * as[f];      e1 += h1 * as[32 + f];
        d0 += h0 * ad[f];      d1 += h1 * ad[32 + f];
    }
    g_es[idx * 2] = e0;  g_es[idx * 2 + 1] = e1;
    g_ed[idx * 2] = d0;  g_ed[idx * 2 + 1] = d1;
}

// ---------------- CSR build (deterministic) ----------------
__global__ void k_zero() {
    int i = blockIdx.x * blockDim.x + threadIdx.x;
    if (i < KN) g_deg[i] = 0;
}
__global__ void k_hist(const int* __restrict__ ei) {
    int e = blockIdx.x * blockDim.x + threadIdx.x;
    if (e < KE) atomicAdd(&g_deg[ei[KE + e]], 1);
}
__global__ __launch_bounds__(1024) void k_scan() {
    __shared__ int wsum[32];
    int t = threadIdx.x;
    int base = t * 4;
    int c[4], s = 0;
    #pragma unroll
    for (int i = 0; i < 4; i++) { c[i] = g_deg[base + i] + 1; s += c[i]; }
    int lane = t & 31, wid = t >> 5;
    int v = s;
    #pragma unroll
    for (int off = 1; off < 32; off <<= 1) {
        int u = __shfl_up_sync(0xffffffffu, v, off);
        if (lane >= off) v += u;
    }
    if (lane == 31) wsum[wid] = v;
    __syncthreads();
    if (t < 32) {
        int w = wsum[t];
        #pragma unroll
        for (int off = 1; off < 32; off <<= 1) {
            int u = __shfl_up_sync(0xffffffffu, w, off);
            if (t >= off) w += u;
        }
        wsum[t] = w;
    }
    __syncthreads();
    int woff = wid ? wsum[wid - 1] : 0;
    int run = woff + v - s;   // exclusive prefix
    #pragma unroll
    for (int i = 0; i < 4; i++) {
        g_rowptr[base + i] = run;
        g_pos[base + i] = run + 1;
        g_srcs[run] = KE + base + i;   // self loop as edge-id E+n (sorts last)
        run += c[i];
    }
    if (t == 1023) g_rowptr[KN] = run;
}
__global__ void k_fill(const int* __restrict__ ei) {
    int e = blockIdx.x * blockDim.x + threadIdx.x;
    if (e < KE) {
        int d = ei[KE + e];
        int slot = atomicAdd(&g_pos[d], 1);
        g_srcs[slot] = e;
    }
}
__global__ void k_sort(const int* __restrict__ ei) {
    int n = blockIdx.x * blockDim.x + threadIdx.x;
    if (n >= KN) return;
    int beg = g_rowptr[n], end = g_rowptr[n + 1];
    for (int i = beg + 1; i < end; i++) {     // insertion sort by edge id
        int key = g_srcs[i];
        int j = i - 1;
        while (j >= beg && g_srcs[j] > key) { g_srcs[j + 1] = g_srcs[j]; j--; }
        g_srcs[j + 1] = key;
    }
    for (int i = beg; i < end; i++) {         // edge id -> src node
        int id = g_srcs[i];
        g_srcs[i] = (id < KE) ? ei[id] : (id - KE);
    }
}

// ---------------- GAT softmax + aggregation (warp per (b,dst)) ----------------
__global__ __launch_bounds__(256) void k_gat(const float* __restrict__ gatB) {
    int w = threadIdx.x >> 5, lane = threadIdx.x & 31;
    int dst = blockIdx.x * 8 + w;
    int b = blockIdx.y;
    int beg = g_rowptr[dst], end = g_rowptr[dst + 1];
    const float* es = g_es + (long long)b * KN * 2;
    const float* ed = g_ed + (long long)b * KN * 2;
    float ed0 = ed[dst * 2], ed1 = ed[dst * 2 + 1];

    float m0 = -1e30f, m1 = -1e30f;
    for (int i = beg + lane; i < end; i += 32) {
        int s = g_srcs[i];
        m0 = fmaxf(m0, lrelu(es[s * 2] + ed0));
        m1 = fmaxf(m1, lrelu(es[s * 2 + 1] + ed1));
    }
    #pragma unroll
    for (int off = 16; off; off >>= 1) {
        m0 = fmaxf(m0, __shfl_xor_sync(0xffffffffu, m0, off));
        m1 = fmaxf(m1, __shfl_xor_sync(0xffffffffu, m1, off));
    }
    float s0 = 0.f, s1 = 0.f;
    for (int i = beg + lane; i < end; i += 32) {
        int s = g_srcs[i];
        s0 += __expf(lrelu(es[s * 2] + ed0) - m0);
        s1 += __expf(lrelu(es[s * 2 + 1] + ed1) - m1);
    }
    #pragma unroll
    for (int off = 16; off; off >>= 1) {
        s0 += __shfl_xor_sync(0xffffffffu, s0, off);
        s1 += __shfl_xor_sync(0xffffffffu, s1, off);
    }
    float inv0 = 1.f / (s0 + 1e-16f), inv1 = 1.f / (s1 + 1e-16f);

    float acc0 = 0.f, acc1 = 0.f;
    for (int i = beg; i < end; i++) {
        int s = g_srcs[i];
        float a0 = __expf(lrelu(es[s * 2] + ed0) - m0) * inv0;
        float a1 = __expf(lrelu(es[s * 2 + 1] + ed1) - m1) * inv1;
        const float* hr = g_h + ((long long)b * KN + s) * 64;
        acc0 += a0 * hr[lane];
        acc1 += a1 * hr[32 + lane];
    }
    float o0 = eluf(acc0 + gatB[b * 64 + lane]);
    float o1 = eluf(acc1 + gatB[b * 64 + 32 + lane]);
    long long o = ((long long)b * KN + dst) * 64;
    g_gat[o + lane] = o0;
    g_gat[o + 32 + lane] = o1;
}

// ---------------- branch MLP ----------------
__global__ __launch_bounds__(256) void k_mlp(const float* __restrict__ mW,
                                             const float* __restrict__ mb) {
    __shared__ float Ws[64 * 64];
    __shared__ float Gs[64 * 64];
    int b = blockIdx.y;
    int rowBase = blockIdx.x * 64;
    int t = threadIdx.x;
    const float* Wb = mW + b * 64 * 64;
    const float* Gb = g_gat + ((long long)b * KN + rowBase) * 64;
    for (int i = t; i < 4096; i += 256) { Ws[i] = Wb[i]; Gs[i] = Gb[i]; }
    __syncthreads();
    int col = t & 63, ns = t >> 6;
    float bias = mb[b * 64 + col];
    for (int i = 0; i < 16; i++) {
        int n = i * 4 + ns;
        float acc = bias;
        #pragma unroll
        for (int k = 0; k < 64; k++) acc += Gs[n * 64 + k] * Ws[k * 64 + col];
        g_feat[(long long)(rowBase + n) * (KG * KNHID) + b * 64 + col] = acc;
    }
}

// ---------------- final head + log_softmax (warp per node) ----------------
__global__ __launch_bounds__(256) void k_final(const float* __restrict__ oW,
                                               const float* __restrict__ ob,
                                               float* __restrict__ out) {
    int w = threadIdx.x >> 5, lane = threadIdx.x & 31;
    int n = blockIdx.x * 8 + w;
    const float* fr = g_feat + (long long)n * (KG * KNHID);
    float acc[KC];
    #pragma unroll
    for (int c = 0; c < KC; c++) acc[c] = 0.f;
    for (int k = lane; k < KG * KNHID; k += 32) {
        float v = eluf(fr[k]);
        #pragma unroll
        for (int c = 0; c < KC; c++) acc[c] += v * oW[k * KC + c];
    }
    #pragma unroll
    for (int c = 0; c < KC; c++)
        #pragma unroll
        for (int off = 16; off; off >>= 1)
            acc[c] += __shfl_xor_sync(0xffffffffu, acc[c], off);
    if (lane == 0) {
        float l[KC], m = -1e30f;
        #pragma unroll
        for (int c = 0; c < KC; c++) { l[c] = acc[c] + ob[c]; m = fmaxf(m, l[c]); }
        float se = 0.f;
        #pragma unroll
        for (int c = 0; c < KC; c++) se += expf(l[c] - m);
        float lse = logf(se) + m;
        #pragma unroll
        for (int c = 0; c < KC; c++) out[(long long)n * KC + c] = l[c] - lse;
    }
}

// ---------------- launch ----------------
static inline int smemBytes(int nb) { return 1024 + 65536 + nb * 4 * 4096; }

extern "C" void kernel_launch(void* const* d_in, const int* in_sizes, int n_in,
                              void* d_out, int out_size) {
    (void)in_sizes; (void)n_in; (void)out_size;
    const float* x     = (const float*)d_in[0];
    const int*   ei    = (const int*)d_in[1];
    const float* U     = (const float*)d_in[2];
    const float* psi   = (const float*)d_in[3];
    const float* gatW  = (const float*)d_in[4];
    const float* att_s = (const float*)d_in[5];
    const float* att_d = (const float*)d_in[6];
    const float* gatB  = (const float*)d_in[7];
    const float* mlpW  = (const float*)d_in[8];
    const float* mlpB  = (const float*)d_in[9];
    const float* outW  = (const float*)d_in[10];
    const float* outB  = (const float*)d_in[11];
    float* out = (float*)d_out;

    cudaFuncSetAttribute(k_mma<1>, cudaFuncAttributeMaxDynamicSharedMemorySize, smemBytes(1));
    cudaFuncSetAttribute(k_mma<2>, cudaFuncAttributeMaxDynamicSharedMemorySize, smemBytes(2));

    k_absT<<<(KN * KF + 255) / 256, 256>>>(x);
    k_convA<<<(int)((4ull * KNN / 4 + 255) / 256), 256>>>(U, psi);

    // scattering transform on tensor cores (mma.sync / HMMA)
    k_mma<1><<<dim3(32, 3), 256, smemBytes(1)>>>(0);   // level 1: psi_y @ |x|
    k_mma<2><<<dim3(32, 3), 256, smemBytes(2)>>>(1);   // level 2: psi_y @ {R1,R2}
    k_mma<1><<<dim3(32, 3), 256, smemBytes(1)>>>(1);   // level 2: psi_y @ {R3}
    k_mma<2><<<dim3(32, 6), 256, smemBytes(2)>>>(2);   // coef: U @ slots {0..11}
    k_mma<1><<<dim3(32, 1), 256, smemBytes(1)>>>(2);   // coef: U @ slot {12}

    // CSR build
    k_zero<<<16, 256>>>();
    k_hist<<<KE / 256, 256>>>(ei);
    k_scan<<<1, 1024>>>();
    k_fill<<<KE / 256, 256>>>(ei);
    k_sort<<<16, 256>>>(ei);

    // 13 GAT branches
    k_h<<<dim3(32, KG), 256>>>(gatW);
    k_esed<<<(KG * KN + 255) / 256, 256>>>(att_s, att_d);
    k_gat<<<dim3(KN / 8, KG), 256>>>(gatB);
    k_mlp<<<dim3(KN / 64, KG), 256>>>(mlpW, mlpB);
    k_final<<<KN / 8, 256>>>(outW, outB, out);
}

// round 5
// speedup vs baseline: 2.9933x; 1.6152x over previous
#include <cuda_runtime.h>
#include <cuda_bf16.h>
#include <cstdint>

// Problem constants
#define KN 4096      // nodes
#define KF 32        // features
#define KHF 64       // heads*features
#define KNHID 64
#define KC 10
#define KE 65536     // edges
#define KG 13        // branches
#define KNN (KN*KN)
#define KNF (KN*KF)

// ---------------- device scratch (no allocations allowed) ----------------
__device__ __align__(128) __nv_bfloat16 g_Ah[4ull * KNN];   // psi0..2, U  (hi)
__device__ __align__(128) __nv_bfloat16 g_Al[4ull * KNN];   // (lo residual)
__device__ __align__(128) __nv_bfloat16 g_Bh[KG * KF * KN]; // B operands [slot][f][node]
__device__ __align__(128) __nv_bfloat16 g_Bl[KG * KF * KN];
__device__ float g_part[9 * KN * KF];    // split-K partials for level 1
__device__ float g_coef[KG * KN * KF];   // [13][N][32]: U @ R
__device__ float g_h[KG * KN * KHF];     // per-branch GAT hidden [13][N][64]
__device__ float g_es[KG * KN * 2];
__device__ float g_ed[KG * KN * 2];
__device__ float g_gat[KG * KN * KHF];   // post-ELU GAT output
__device__ float g_feat[KN * KG * KNHID];// [N][832]
__device__ int   g_deg[KN];
__device__ int   g_rowptr[KN + 1];
__device__ int   g_pos[KN];
__device__ int   g_srcs[KE + KN];

// ---------------- helpers ----------------
__device__ __forceinline__ float lrelu(float v) { return v > 0.f ? v : 0.2f * v; }
__device__ __forceinline__ float eluf(float v)  { return v > 0.f ? v : expm1f(v); }

__device__ __forceinline__ uint32_t su32(const void* p) {
    return (uint32_t)__cvta_generic_to_shared(p);
}
__device__ __forceinline__ void cpa16(uint32_t dst, const void* src) {
    asm volatile("cp.async.cg.shared.global [%0], [%1], 16;" :: "r"(dst), "l"(src) : "memory");
}
__device__ __forceinline__ uint32_t swz64(uint32_t off) { return off ^ ((off >> 3) & 0x30); }

#define LDSM4(d, addr) \
    asm volatile("ldmatrix.sync.aligned.m8n8.x4.shared.b16 {%0,%1,%2,%3}, [%4];" \
        : "=r"((d)[0]), "=r"((d)[1]), "=r"((d)[2]), "=r"((d)[3]) : "r"(addr))

__device__ __forceinline__ void mma_bf16(float* c, const uint32_t* a,
                                         uint32_t b0, uint32_t b1) {
    asm volatile("mma.sync.aligned.m16n8k16.row.col.f32.bf16.bf16.f32 "
        "{%0,%1,%2,%3}, {%4,%5,%6,%7}, {%8,%9}, {%0,%1,%2,%3};"
        : "+f"(c[0]), "+f"(c[1]), "+f"(c[2]), "+f"(c[3])
        : "r"(a[0]), "r"(a[1]), "r"(a[2]), "r"(a[3]), "r"(b0), "r"(b1));
}

// ---------------- |x| -> transposed bf16 split (B slot 0) ----------------
__global__ void k_absT(const float* __restrict__ x) {
    int i = blockIdx.x * 256 + threadIdx.x;
    if (i >= KN * KF) return;
    int node = i >> 5, f = i & 31;
    float v = fabsf(x[i]);
    __nv_bfloat16 h = __float2bfloat16(v);
    g_Bh[f * KN + node] = h;
    g_Bl[f * KN + node] = __float2bfloat16(v - __bfloat162float(h));
}

// ---------------- psi/U fp32 -> bf16 hi/lo ----------------
__global__ __launch_bounds__(256) void k_convA(const float* __restrict__ U,
                                               const float* __restrict__ psi) {
    size_t i = ((size_t)blockIdx.x * 256 + threadIdx.x) * 4;
    if (i >= 4ull * KNN) return;
    float4 v = (i < 3ull * KNN) ? *(const float4*)(psi + i)
                                : *(const float4*)(U + (i - 3ull * KNN));
    __nv_bfloat16 h0 = __float2bfloat16(v.x), h1 = __float2bfloat16(v.y);
    __nv_bfloat16 h2 = __float2bfloat16(v.z), h3 = __float2bfloat16(v.w);
    __nv_bfloat162* ph = (__nv_bfloat162*)(g_Ah + i);
    ph[0] = __nv_bfloat162(h0, h1);  ph[1] = __nv_bfloat162(h2, h3);
    __nv_bfloat162* pl = (__nv_bfloat162*)(g_Al + i);
    pl[0] = __nv_bfloat162(__float2bfloat16(v.x - __bfloat162float(h0)),
                           __float2bfloat16(v.y - __bfloat162float(h1)));
    pl[1] = __nv_bfloat162(__float2bfloat16(v.z - __bfloat162float(h2)),
                           __float2bfloat16(v.w - __bfloat162float(h3)));
}

// ---------------- level-1 split-K reduce: |p0+p1+p2| -> slots 1..3 ----------------
__global__ void k_red1() {
    int i = blockIdx.x * 256 + threadIdx.x;
    if (i >= 3 * KN * KF) return;
    int y = i / (KN * KF);
    int rem = i - y * (KN * KF);
    int node = rem >> 5, f = rem & 31;
    size_t o = (size_t)y * (KN * KF) + rem - (size_t)y * (KN * KF) + (size_t)y * (KN * KF);
    o = (size_t)y * (KN * KF) + (size_t)node * KF + f;
    float v = fabsf(g_part[o] + g_part[o + (size_t)3 * KN * KF] + g_part[o + (size_t)6 * KN * KF]);
    __nv_bfloat16 h = __float2bfloat16(v);
    size_t ob = (size_t)(1 + y) * (KF * KN) + (size_t)f * KN + node;
    g_Bh[ob] = h;
    g_Bl[ob] = __float2bfloat16(v - __bfloat162float(h));
}

// ---------------- mma.sync scattering GEMM ----------------
// C[128-tile, NB*32] = A[128, K-range] @ B^T, 3-part bf16 split, K-chunks of 32,
// 3-stage cp.async ring. 8 warps = 4(M) x 2(N), warp tile m32 x (NB*16).
// mode 0 (NB1): L1 split-K: A=psi_y, in slot0, raw fp32 -> g_part[z*3+y]. grid (32,3,3)
// mode 1 (NB1): L2: A=psi_{y%3}, in 1+y/3, out 4+y, abs-split. grid (32,9)
// mode 2 (NB2): coef: A=U, slots {2y, min(2y+1,12)}, fp32 -> g_coef. grid (32,7)
template <int NB>
__global__ __launch_bounds__(256, 2) void k_mma(int mode) {
    extern __shared__ char dsm[];
    int tid = threadIdx.x;
    uint32_t sbase = (su32(dsm) + 1023u) & ~1023u;

    int y = blockIdx.y;
    int rowBase = blockIdx.x * 128;
    int slotIn[NB], slotOut[NB];
    const __nv_bfloat16* Ah;
    int outKind;                 // 0 = abs-split, 1 = fp32 coef, 2 = raw partial
    int cBeg = 0, cEnd = 128;    // chunk32 indices
    float* rawOut = nullptr;
    if (mode == 0) {
        Ah = g_Ah + (size_t)y * KNN; slotIn[0] = 0; slotOut[0] = 0; outKind = 2;
        int z = blockIdx.z;
        cBeg = (z * 128) / 3; cEnd = ((z + 1) * 128) / 3;
        rawOut = g_part + (size_t)(z * 3 + y) * (KN * KF);
    } else if (mode == 1) {
        Ah = g_Ah + (size_t)(y % 3) * KNN;
        slotIn[0] = 1 + y / 3; slotOut[0] = 4 + y; outKind = 0;
    } else {
        Ah = g_Ah + (size_t)3 * KNN;
        slotIn[0] = 2 * y; slotOut[0] = 2 * y;
        if (NB == 2) {
            int s1 = (2 * y + 1 > 12) ? 12 : (2 * y + 1);
            slotIn[NB - 1] = s1; slotOut[NB - 1] = s1;
        }
        outKind = 1;
    }
    const __nv_bfloat16* Al = g_Al + (Ah - g_Ah);

    // smem: A(stage,part) 8KB x6 = 48KB, then B(stage,part,b) 2KB each
    auto A_at = [&](int st, int p) { return sbase + (uint32_t)(st * 2 + p) * 8192u; };
    auto B_at = [&](int st, int p, int b) {
        return sbase + 49152u + (uint32_t)((st * 2 + p) * NB + b) * 2048u;
    };

    auto ldChunk = [&](int c, int s) {
        int k0 = c * 32;
        #pragma unroll
        for (int i0 = 0; i0 < 2; i0++) {   // A: 512 16B segs x 2 parts
            int i = i0 * 256 + tid;
            int r = i >> 2, seg = i & 3;
            uint32_t sw = swz64((uint32_t)(r * 64 + seg * 16));
            size_t go = (size_t)(rowBase + r) * KN + k0 + seg * 8;
            cpa16(A_at(s, 0) + sw, Ah + go);
            cpa16(A_at(s, 1) + sw, Al + go);
        }
        if (tid < 128) {                   // B: 128 16B segs x 2 parts per branch
            int r = tid >> 2, seg = tid & 3;
            uint32_t sw = swz64((uint32_t)(r * 64 + seg * 16));
            #pragma unroll
            for (int b = 0; b < NB; b++) {
                size_t go = (size_t)slotIn[b] * (KF * KN) + (size_t)r * KN + k0 + seg * 8;
                cpa16(B_at(s, 0, b) + sw, g_Bh + go);
                cpa16(B_at(s, 1, b) + sw, g_Bl + go);
            }
        }
    };

    int wid = tid >> 5, lane = tid & 31;
    int wm = wid >> 1, wn = wid & 1;       // 4 M-warps x 2 N-warps

    auto aAddr = [&](uint32_t base, int mt, int q) {
        int row = wm * 32 + mt * 16 + (lane & 15);
        int colb = q * 32 + ((lane >> 4) << 4);
        return base + swz64((uint32_t)(row * 64 + colb));
    };
    auto bAddr = [&](uint32_t base, int n0, int q) {
        int j = lane >> 3, r = lane & 7;
        int row = n0 + ((j >> 1) << 3) + r;
        int colb = q * 32 + ((j & 1) << 4);
        return base + swz64((uint32_t)(row * 64 + colb));
    };

    float acc[2][2 * NB][4];
    #pragma unroll
    for (int mt = 0; mt < 2; mt++)
        #pragma unroll
        for (int n = 0; n < 2 * NB; n++)
            #pragma unroll
            for (int e = 0; e < 4; e++) acc[mt][n][e] = 0.f;

    ldChunk(cBeg, 0);
    asm volatile("cp.async.commit_group;" ::: "memory");
    if (cBeg + 1 < cEnd) ldChunk(cBeg + 1, 1);
    asm volatile("cp.async.commit_group;" ::: "memory");

    for (int i = cBeg; i < cEnd; i++) {
        int s = (i - cBeg) % 3;
        asm volatile("cp.async.wait_group 1;" ::: "memory");
        __syncthreads();
        if (i + 2 < cEnd) ldChunk(i + 2, (i - cBeg + 2) % 3);
        asm volatile("cp.async.commit_group;" ::: "memory");

        #pragma unroll
        for (int q = 0; q < 2; q++) {      // k16 steps
            uint32_t ah[2][4], al[2][4];
            #pragma unroll
            for (int mt = 0; mt < 2; mt++) {
                LDSM4(ah[mt], aAddr(A_at(s, 0), mt, q));
                LDSM4(al[mt], aAddr(A_at(s, 1), mt, q));
            }
            #pragma unroll
            for (int t16 = 0; t16 < NB; t16++) {
                int g16 = wn * NB + t16;
                int b = g16 >> 1, n0 = (g16 & 1) * 16;
                uint32_t bh[4], bl[4];
                LDSM4(bh, bAddr(B_at(s, 0, b), n0, q));
                LDSM4(bl, bAddr(B_at(s, 1, b), n0, q));
                #pragma unroll
                for (int n8 = 0; n8 < 2; n8++) {
                    uint32_t h0 = bh[2 * n8], h1 = bh[2 * n8 + 1];
                    uint32_t l0 = bl[2 * n8], l1 = bl[2 * n8 + 1];
                    #pragma unroll
                    for (int mt = 0; mt < 2; mt++) {
                        float* c = acc[mt][t16 * 2 + n8];
                        mma_bf16(c, ah[mt], h0, h1);
                        mma_bf16(c, ah[mt], l0, l1);
                        mma_bf16(c, al[mt], h0, h1);
                    }
                }
            }
        }
    }

    // epilogue
    int quad = lane >> 2, tq = lane & 3;
    #pragma unroll
    for (int mt = 0; mt < 2; mt++) {
        int rBase = rowBase + wm * 32 + mt * 16 + quad;
        #pragma unroll
        for (int t16 = 0; t16 < NB; t16++) {
            int g16 = wn * NB + t16;
            int b = g16 >> 1;
            #pragma unroll
            for (int n8 = 0; n8 < 2; n8++) {
                float* c = acc[mt][t16 * 2 + n8];
                int f0 = (g16 & 1) * 16 + n8 * 8 + tq * 2;
                if (outKind == 0) {
                    size_t sb = (size_t)slotOut[b] * (KF * KN);
                    #pragma unroll
                    for (int e = 0; e < 4; e++) {
                        int row = rBase + ((e >> 1) << 3);
                        int f = f0 + (e & 1);
                        float v = fabsf(c[e]);
                        __nv_bfloat16 h = __float2bfloat16(v);
                        size_t o = sb + (size_t)f * KN + row;
                        g_Bh[o] = h;
                        g_Bl[o] = __float2bfloat16(v - __bfloat162float(h));
                    }
                } else if (outKind == 1) {
                    size_t sb = (size_t)slotOut[b] * KN;
                    #pragma unroll
                    for (int e = 0; e < 4; e++) {
                        int row = rBase + ((e >> 1) << 3);
                        int f = f0 + (e & 1);
                        g_coef[(sb + row) * KF + f] = c[e];
                    }
                } else {
                    #pragma unroll
                    for (int e = 0; e < 4; e++) {
                        int row = rBase + ((e >> 1) << 3);
                        int f = f0 + (e & 1);
                        rawOut[(size_t)row * KF + f] = c[e];
                    }
                }
            }
        }
    }
}

// ---------------- h = coef[b] @ gat_W[b]  ([N,32]@[32,64]) ----------------
__global__ __launch_bounds__(256) void k_h(const float* __restrict__ gatW) {
    __shared__ float Ws[32 * 64];
    __shared__ float Cs[128 * 32];
    int b = blockIdx.y;
    int rowBase = blockIdx.x * 128;
    int t = threadIdx.x;
    const float* Wb = gatW + b * 32 * 64;
    const float* Cb = g_coef + (long long)b * KNF + (long long)rowBase * KF;
    for (int i = t; i < 2048; i += 256) Ws[i] = Wb[i];
    for (int i = t; i < 4096; i += 256) Cs[i] = Cb[i];
    __syncthreads();
    int col = t & 63, ns = t >> 6;
    for (int i = 0; i < 32; i++) {
        int n = i * 4 + ns;
        float acc = 0.f;
        #pragma unroll
        for (int k = 0; k < 32; k++) acc += Cs[n * 32 + k] * Ws[k * 64 + col];
        g_h[((long long)b * KN + rowBase + n) * 64 + col] = acc;
    }
}

// ---------------- attention logits es/ed ----------------
__global__ void k_esed(const float* __restrict__ att_s, const float* __restrict__ att_d) {
    int idx = blockIdx.x * blockDim.x + threadIdx.x;
    if (idx >= KG * KN) return;
    int b = idx / KN;
    const float* hr = g_h + (long long)idx * 64;
    const float* as = att_s + b * 64;
    const float* ad = att_d + b * 64;
    float e0 = 0, e1 = 0, d0 = 0, d1 = 0;
    #pragma unroll
    for (int f = 0; f < 32; f++) {
        float h0 = hr[f], h1 = hr[32 + f];
        e0 += h0 * as[f];      e1 += h1 * as[32 + f];
        d0 += h0 * ad[f];      d1 += h1 * ad[32 + f];
    }
    g_es[idx * 2] = e0;  g_es[idx * 2 + 1] = e1;
    g_ed[idx * 2] = d0;  g_ed[idx * 2 + 1] = d1;
}

// ---------------- CSR build (deterministic) ----------------
__global__ void k_zero() {
    int i = blockIdx.x * blockDim.x + threadIdx.x;
    if (i < KN) g_deg[i] = 0;
}
__global__ void k_hist(const int* __restrict__ ei) {
    int e = blockIdx.x * blockDim.x + threadIdx.x;
    if (e < KE) atomicAdd(&g_deg[ei[KE + e]], 1);
}
__global__ __launch_bounds__(1024) void k_scan() {
    __shared__ int wsum[32];
    int t = threadIdx.x;
    int base = t * 4;
    int c[4], s = 0;
    #pragma unroll
    for (int i = 0; i < 4; i++) { c[i] = g_deg[base + i] + 1; s += c[i]; }
    int lane = t & 31, wid = t >> 5;
    int v = s;
    #pragma unroll
    for (int off = 1; off < 32; off <<= 1) {
        int u = __shfl_up_sync(0xffffffffu, v, off);
        if (lane >= off) v += u;
    }
    if (lane == 31) wsum[wid] = v;
    __syncthreads();
    if (t < 32) {
        int w = wsum[t];
        #pragma unroll
        for (int off = 1; off < 32; off <<= 1) {
            int u = __shfl_up_sync(0xffffffffu, w, off);
            if (t >= off) w += u;
        }
        wsum[t] = w;
    }
    __syncthreads();
    int woff = wid ? wsum[wid - 1] : 0;
    int run = woff + v - s;   // exclusive prefix
    #pragma unroll
    for (int i = 0; i < 4; i++) {
        g_rowptr[base + i] = run;
        g_pos[base + i] = run + 1;
        g_srcs[run] = KE + base + i;   // self loop as edge-id E+n (sorts last)
        run += c[i];
    }
    if (t == 1023) g_rowptr[KN] = run;
}
__global__ void k_fill(const int* __restrict__ ei) {
    int e = blockIdx.x * blockDim.x + threadIdx.x;
    if (e < KE) {
        int d = ei[KE + e];
        int slot = atomicAdd(&g_pos[d], 1);
        g_srcs[slot] = e;
    }
}
__global__ void k_sort(const int* __restrict__ ei) {
    int n = blockIdx.x * blockDim.x + threadIdx.x;
    if (n >= KN) return;
    int beg = g_rowptr[n], end = g_rowptr[n + 1];
    for (int i = beg + 1; i < end; i++) {     // insertion sort by edge id
        int key = g_srcs[i];
        int j = i - 1;
        while (j >= beg && g_srcs[j] > key) { g_srcs[j + 1] = g_srcs[j]; j--; }
        g_srcs[j + 1] = key;
    }
    for (int i = beg; i < end; i++) {         // edge id -> src node
        int id = g_srcs[i];
        g_srcs[i] = (id < KE) ? ei[id] : (id - KE);
    }
}

// ---------------- GAT softmax + aggregation (warp per (b,dst)) ----------------
__global__ __launch_bounds__(256) void k_gat(const float* __restrict__ gatB) {
    int w = threadIdx.x >> 5, lane = threadIdx.x & 31;
    int dst = blockIdx.x * 8 + w;
    int b = blockIdx.y;
    int beg = g_rowptr[dst], end = g_rowptr[dst + 1];
    const float* es = g_es + (long long)b * KN * 2;
    const float* ed = g_ed + (long long)b * KN * 2;
    float ed0 = ed[dst * 2], ed1 = ed[dst * 2 + 1];

    float m0 = -1e30f, m1 = -1e30f;
    for (int i = beg + lane; i < end; i += 32) {
        int s = g_srcs[i];
        m0 = fmaxf(m0, lrelu(es[s * 2] + ed0));
        m1 = fmaxf(m1, lrelu(es[s * 2 + 1] + ed1));
    }
    #pragma unroll
    for (int off = 16; off; off >>= 1) {
        m0 = fmaxf(m0, __shfl_xor_sync(0xffffffffu, m0, off));
        m1 = fmaxf(m1, __shfl_xor_sync(0xffffffffu, m1, off));
    }
    float s0 = 0.f, s1 = 0.f;
    for (int i = beg + lane; i < end; i += 32) {
        int s = g_srcs[i];
        s0 += __expf(lrelu(es[s * 2] + ed0) - m0);
        s1 += __expf(lrelu(es[s * 2 + 1] + ed1) - m1);
    }
    #pragma unroll
    for (int off = 16; off; off >>= 1) {
        s0 += __shfl_xor_sync(0xffffffffu, s0, off);
        s1 += __shfl_xor_sync(0xffffffffu, s1, off);
    }
    float inv0 = 1.f / (s0 + 1e-16f), inv1 = 1.f / (s1 + 1e-16f);

    float acc0 = 0.f, acc1 = 0.f;
    for (int i = beg; i < end; i++) {
        int s = g_srcs[i];
        float a0 = __expf(lrelu(es[s * 2] + ed0) - m0) * inv0;
        float a1 = __expf(lrelu(es[s * 2 + 1] + ed1) - m1) * inv1;
        const float* hr = g_h + ((long long)b * KN + s) * 64;
        acc0 += a0 * hr[lane];
        acc1 += a1 * hr[32 + lane];
    }
    float o0 = eluf(acc0 + gatB[b * 64 + lane]);
    float o1 = eluf(acc1 + gatB[b * 64 + 32 + lane]);
    long long o = ((long long)b * KN + dst) * 64;
    g_gat[o + lane] = o0;
    g_gat[o + 32 + lane] = o1;
}

// ---------------- branch MLP ----------------
__global__ __launch_bounds__(256) void k_mlp(const float* __restrict__ mW,
                                             const float* __restrict__ mb) {
    __shared__ float Ws[64 * 64];
    __shared__ float Gs[64 * 64];
    int b = blockIdx.y;
    int rowBase = blockIdx.x * 64;
    int t = threadIdx.x;
    const float* Wb = mW + b * 64 * 64;
    const float* Gb = g_gat + ((long long)b * KN + rowBase) * 64;
    for (int i = t; i < 4096; i += 256) { Ws[i] = Wb[i]; Gs[i] = Gb[i]; }
    __syncthreads();
    int col = t & 63, ns = t >> 6;
    float bias = mb[b * 64 + col];
    for (int i = 0; i < 16; i++) {
        int n = i * 4 + ns;
        float acc = bias;
        #pragma unroll
        for (int k = 0; k < 64; k++) acc += Gs[n * 64 + k] * Ws[k * 64 + col];
        g_feat[(long long)(rowBase + n) * (KG * KNHID) + b * 64 + col] = acc;
    }
}

// ---------------- final head + log_softmax (warp per node) ----------------
__global__ __launch_bounds__(256) void k_final(const float* __restrict__ oW,
                                               const float* __restrict__ ob,
                                               float* __restrict__ out) {
    int w = threadIdx.x >> 5, lane = threadIdx.x & 31;
    int n = blockIdx.x * 8 + w;
    const float* fr = g_feat + (long long)n * (KG * KNHID);
    float acc[KC];
    #pragma unroll
    for (int c = 0; c < KC; c++) acc[c] = 0.f;
    for (int k = lane; k < KG * KNHID; k += 32) {
        float v = eluf(fr[k]);
        #pragma unroll
        for (int c = 0; c < KC; c++) acc[c] += v * oW[k * KC + c];
    }
    #pragma unroll
    for (int c = 0; c < KC; c++)
        #pragma unroll
        for (int off = 16; off; off >>= 1)
            acc[c] += __shfl_xor_sync(0xffffffffu, acc[c], off);
    if (lane == 0) {
        float l[KC], m = -1e30f;
        #pragma unroll
        for (int c = 0; c < KC; c++) { l[c] = acc[c] + ob[c]; m = fmaxf(m, l[c]); }
        float se = 0.f;
        #pragma unroll
        for (int c = 0; c < KC; c++) se += expf(l[c] - m);
        float lse = logf(se) + m;
        #pragma unroll
        for (int c = 0; c < KC; c++) out[(long long)n * KC + c] = l[c] - lse;
    }
}

// ---------------- launch ----------------
static inline int smemBytes(int nb) { return 1024 + 49152 + nb * 6 * 2048; }

extern "C" void kernel_launch(void* const* d_in, const int* in_sizes, int n_in,
                              void* d_out, int out_size) {
    (void)in_sizes; (void)n_in; (void)out_size;
    const float* x     = (const float*)d_in[0];
    const int*   ei    = (const int*)d_in[1];
    const float* U     = (const float*)d_in[2];
    const float* psi   = (const float*)d_in[3];
    const float* gatW  = (const float*)d_in[4];
    const float* att_s = (const float*)d_in[5];
    const float* att_d = (const float*)d_in[6];
    const float* gatB  = (const float*)d_in[7];
    const float* mlpW  = (const float*)d_in[8];
    const float* mlpB  = (const float*)d_in[9];
    const float* outW  = (const float*)d_in[10];
    const float* outB  = (const float*)d_in[11];
    float* out = (float*)d_out;

    cudaFuncSetAttribute(k_mma<1>, cudaFuncAttributeMaxDynamicSharedMemorySize, smemBytes(1));
    cudaFuncSetAttribute(k_mma<2>, cudaFuncAttributeMaxDynamicSharedMemorySize, smemBytes(2));
    cudaFuncSetAttribute(k_mma<1>, cudaFuncAttributePreferredSharedMemoryCarveout, 100);
    cudaFuncSetAttribute(k_mma<2>, cudaFuncAttributePreferredSharedMemoryCarveout, 100);

    k_absT<<<(KN * KF + 255) / 256, 256>>>(x);
    k_convA<<<(int)((4ull * KNN / 4 + 255) / 256), 256>>>(U, psi);

    // scattering transform on tensor cores (mma.sync / HMMA)
    k_mma<1><<<dim3(32, 3, 3), 256, smemBytes(1)>>>(0);  // L1 split-K: 288 CTAs
    k_red1<<<(3 * KN * KF + 255) / 256, 256>>>();        // combine + abs + split
    k_mma<1><<<dim3(32, 9), 256, smemBytes(1)>>>(1);     // L2: 288 CTAs
    k_mma<2><<<dim3(32, 7), 256, smemBytes(2)>>>(2);     // coef: 224 CTAs

    // CSR build
    k_zero<<<16, 256>>>();
    k_hist<<<KE / 256, 256>>>(ei);
    k_scan<<<1, 1024>>>();
    k_fill<<<KE / 256, 256>>>(ei);
    k_sort<<<16, 256>>>(ei);

    // 13 GAT branches
    k_h<<<dim3(32, KG), 256>>>(gatW);
    k_esed<<<(KG * KN + 255) / 256, 256>>>(att_s, att_d);
    k_gat<<<dim3(KN / 8, KG), 256>>>(gatB);
    k_mlp<<<dim3(KN / 64, KG), 256>>>(mlpW, mlpB);
    k_final<<<KN / 8, 256>>>(outW, outB, out);
}